// round 2
// baseline (speedup 1.0000x reference)
#include <cuda_runtime.h>
#include <cstdint>
#include <cstddef>

// ---------------- problem constants ----------------
#define BATCH  256
#define DMODEL 512
#define DA     256
#define DB     256
#define RR     8
#define NP     2048
#define DP     4608
#define SA     4
#define DKK    64
#define HIDN   1024

// output layout (flattened tuple: output, alpha, W_assembled, keys)
#define OUT_ALPHA  (BATCH*DMODEL)                       // 131072
#define OUT_W      (OUT_ALPHA + BATCH*NP)               // 655360
#define OUT_KEYS   (OUT_W + (size_t)BATCH*DB*DA)        // 17432576

// ---------------- scratch (device globals; no allocation allowed) ----------------
__device__ float g_hid [BATCH*HIDN];
__device__ float g_hA  [BATCH*DA];
__device__ float g_qw  [BATCH*SA*DKK];
__device__ float g_kn  [NP*SA*DKK];
__device__ float g_bt  [BATCH*DB];
__device__ float g_hmid[BATCH*DA];
__device__ float g_hid2[BATCH*HIDN];
__device__ float g_UV  [134217728];   // 2048 * 256 * 256 (537 MB)

// ---------------- helpers ----------------
__device__ __forceinline__ float gelu_f(float x) {
    const float c = 0.7978845608028654f;
    return 0.5f * x * (1.0f + tanhf(c * (x + 0.044715f * x * x * x)));
}

__device__ __forceinline__ unsigned long long dupf2(float a) {
    unsigned long long r; unsigned int u = __float_as_uint(a);
    asm("mov.b64 %0, {%1, %1};" : "=l"(r) : "r"(u));
    return r;
}
__device__ __forceinline__ void fma2(unsigned long long& d, unsigned long long a, unsigned long long b) {
    asm("fma.rn.f32x2 %0, %1, %2, %0;" : "+l"(d) : "l"(a), "l"(b));
}
__device__ __forceinline__ float2 unpk(unsigned long long v) {
    unsigned int lo, hi;
    asm("mov.b64 {%0, %1}, %2;" : "=r"(lo), "=r"(hi) : "l"(v));
    return make_float2(__uint_as_float(lo), __uint_as_float(hi));
}

// ---------------- generic 64x64x16 SGEMM, row-major A[M,K] B[K,N], C=act(A@B+bias) ----------------
template <int ACT>
__global__ void gemm64(const float* __restrict__ A, const float* __restrict__ B,
                       const float* __restrict__ bias, float* __restrict__ C,
                       int K, int lda, int ldb, int ldc)
{
    __shared__ float As[16][64];
    __shared__ float Bs[16][64];
    int tid = threadIdx.x;
    int m0 = blockIdx.y * 64, n0 = blockIdx.x * 64;
    int am = tid >> 2, ak = (tid & 3) * 4;
    int bk = tid >> 4, bn = (tid & 15) * 4;
    int ty = tid >> 4, tx = tid & 15;
    float acc[4][4] = {};
    const float* Ap = A + (size_t)(m0 + am) * lda + ak;
    const float* Bp = B + (size_t)bk * ldb + n0 + bn;
    float4 av = *(const float4*)Ap;
    float4 bv = *(const float4*)Bp;
    for (int k0 = 0; k0 < K; k0 += 16) {
        As[ak + 0][am] = av.x; As[ak + 1][am] = av.y; As[ak + 2][am] = av.z; As[ak + 3][am] = av.w;
        *(float4*)&Bs[bk][bn] = bv;
        __syncthreads();
        if (k0 + 16 < K) {
            av = *(const float4*)(Ap + (k0 + 16));
            bv = *(const float4*)(Bp + (size_t)(k0 + 16) * ldb);
        }
#pragma unroll
        for (int kk = 0; kk < 16; kk++) {
            float ar[4], br[4];
            *(float4*)ar = *(const float4*)&As[kk][ty * 4];
            *(float4*)br = *(const float4*)&Bs[kk][tx * 4];
#pragma unroll
            for (int i = 0; i < 4; i++)
#pragma unroll
                for (int j = 0; j < 4; j++) acc[i][j] += ar[i] * br[j];
        }
        __syncthreads();
    }
#pragma unroll
    for (int i = 0; i < 4; i++) {
        int m = m0 + ty * 4 + i;
#pragma unroll
        for (int j = 0; j < 4; j++) {
            int n = n0 + tx * 4 + j;
            float c = acc[i][j];
            if (bias) c += bias[n];
            if (ACT == 1) c = gelu_f(c);
            C[(size_t)m * ldc + n] = c;
        }
    }
}

// ---------------- keys GEMM: keys[n, a*64+q] = sum_p pool[n,p] * W_K[a,p,q] ----------------
__global__ void keys_gemm_kernel(const float* __restrict__ pool, const float* __restrict__ WK,
                                 float* __restrict__ keys)
{
    int a  = blockIdx.x;           // aspect
    int m0 = blockIdx.y * 64;      // n-tile
    const float* B = WK + (size_t)a * DP * DKK;  // [4608 x 64]
    __shared__ float As[16][64];
    __shared__ float Bs[16][64];
    int tid = threadIdx.x;
    int am = tid >> 2, ak = (tid & 3) * 4;
    int bk = tid >> 4, bn = (tid & 15) * 4;
    int ty = tid >> 4, tx = tid & 15;
    float acc[4][4] = {};
    const float* Ap = pool + (size_t)(m0 + am) * DP + ak;
    const float* Bp = B + (size_t)bk * DKK + bn;
    float4 av = *(const float4*)Ap;
    float4 bv = *(const float4*)Bp;
    for (int k0 = 0; k0 < DP; k0 += 16) {
        As[ak + 0][am] = av.x; As[ak + 1][am] = av.y; As[ak + 2][am] = av.z; As[ak + 3][am] = av.w;
        *(float4*)&Bs[bk][bn] = bv;
        __syncthreads();
        if (k0 + 16 < DP) {
            av = *(const float4*)(Ap + (k0 + 16));
            bv = *(const float4*)(Bp + (size_t)(k0 + 16) * DKK);
        }
#pragma unroll
        for (int kk = 0; kk < 16; kk++) {
            float ar[4], br[4];
            *(float4*)ar = *(const float4*)&As[kk][ty * 4];
            *(float4*)br = *(const float4*)&Bs[kk][tx * 4];
#pragma unroll
            for (int i = 0; i < 4; i++)
#pragma unroll
                for (int j = 0; j < 4; j++) acc[i][j] += ar[i] * br[j];
        }
        __syncthreads();
    }
#pragma unroll
    for (int i = 0; i < 4; i++)
#pragma unroll
        for (int j = 0; j < 4; j++)
            keys[(size_t)(m0 + ty * 4 + i) * (SA * DKK) + a * DKK + tx * 4 + j] = acc[i][j];
}

// ---------------- queries: qw[b, a*64+q] = softmax(logits)[a] * q_norm ----------------
__global__ void q_kernel(const float* __restrict__ hA, const float* __restrict__ WQ,
                         const float* __restrict__ logits, float* __restrict__ qw)
{
    int b = blockIdx.x, a = blockIdx.y, tid = threadIdx.x;  // 64 threads
    __shared__ float hs[DA];
    for (int i = tid; i < DA; i += 64) hs[i] = hA[(size_t)b * DA + i];
    __syncthreads();
    float q = 0.0f;
    const float* w = WQ + (size_t)a * DA * DKK + tid;
#pragma unroll 4
    for (int d = 0; d < DA; d++) q += hs[d] * w[(size_t)d * DKK];
    float ss = q * q;
#pragma unroll
    for (int o = 16; o; o >>= 1) ss += __shfl_xor_sync(0xffffffffu, ss, o);
    __shared__ float r2[2];
    if ((tid & 31) == 0) r2[tid >> 5] = ss;
    __syncthreads();
    float nrm = sqrtf(r2[0] + r2[1]);
    float l0 = logits[0], l1 = logits[1], l2 = logits[2], l3 = logits[3];
    float m = fmaxf(fmaxf(l0, l1), fmaxf(l2, l3));
    float e0 = expf(l0 - m), e1 = expf(l1 - m), e2 = expf(l2 - m), e3 = expf(l3 - m);
    float ea = (a == 0) ? e0 : (a == 1) ? e1 : (a == 2) ? e2 : e3;
    float wa = ea / (e0 + e1 + e2 + e3);
    qw[(size_t)b * (SA * DKK) + a * DKK + tid] = wa * q / (nrm + 1e-8f);
}

// ---------------- key normalization ----------------
__global__ void knorm_kernel(const float* __restrict__ keys, float* __restrict__ kn)
{
    int n = blockIdx.x, a = blockIdx.y, tid = threadIdx.x;  // 64 threads
    size_t idx = (size_t)n * (SA * DKK) + a * DKK + tid;
    float v = keys[idx];
    float ss = v * v;
#pragma unroll
    for (int o = 16; o; o >>= 1) ss += __shfl_xor_sync(0xffffffffu, ss, o);
    __shared__ float r2[2];
    if ((tid & 31) == 0) r2[tid >> 5] = ss;
    __syncthreads();
    float nrm = sqrtf(r2[0] + r2[1]);
    kn[idx] = v / (nrm + 1e-8f);
}

// ---------------- scores (NT gemm 256x2048xK256) + gate/exp epilogue -> alpha_raw ----------------
__global__ void scores_kernel(const float* __restrict__ QW, const float* __restrict__ KN,
                              const float* __restrict__ tau_p, float* __restrict__ alpha)
{
    int n0 = blockIdx.x * 64, m0 = blockIdx.y * 64;
    __shared__ float As[16][64];
    __shared__ float Bs[16][64];
    int tid = threadIdx.x;
    int am = tid >> 2, ak = (tid & 3) * 4;
    int bn = tid >> 2, bk = (tid & 3) * 4;
    int ty = tid >> 4, tx = tid & 15;
    float acc[4][4] = {};
    for (int k0 = 0; k0 < 256; k0 += 16) {
        float4 av = *(const float4*)(QW + (size_t)(m0 + am) * 256 + k0 + ak);
        As[ak + 0][am] = av.x; As[ak + 1][am] = av.y; As[ak + 2][am] = av.z; As[ak + 3][am] = av.w;
        float4 bv = *(const float4*)(KN + (size_t)(n0 + bn) * 256 + k0 + bk);
        Bs[bk + 0][bn] = bv.x; Bs[bk + 1][bn] = bv.y; Bs[bk + 2][bn] = bv.z; Bs[bk + 3][bn] = bv.w;
        __syncthreads();
#pragma unroll
        for (int kk = 0; kk < 16; kk++) {
            float ar[4], br[4];
            *(float4*)ar = *(const float4*)&As[kk][ty * 4];
            *(float4*)br = *(const float4*)&Bs[kk][tx * 4];
#pragma unroll
            for (int i = 0; i < 4; i++)
#pragma unroll
                for (int j = 0; j < 4; j++) acc[i][j] += ar[i] * br[j];
        }
        __syncthreads();
    }
    float tau = tau_p[0];
#pragma unroll
    for (int i = 0; i < 4; i++)
#pragma unroll
        for (int j = 0; j < 4; j++) {
            float s = acc[i][j];
            float g = 1.0f / (1.0f + expf(-(s - tau)));   // LAMBDA_SHARP = 1
            alpha[(size_t)(m0 + ty * 4 + i) * NP + n0 + tx * 4 + j] = g * expf(s);  // TEMP = 1
        }
}

// ---------------- alpha row normalization ----------------
__global__ void alpha_norm_kernel(float* __restrict__ alpha)
{
    int b = blockIdx.x, tid = threadIdx.x;  // 256 threads
    float* row = alpha + (size_t)b * NP;
    float loc[8]; float s = 0.0f;
#pragma unroll
    for (int i = 0; i < 8; i++) { loc[i] = row[tid + 256 * i]; s += loc[i]; }
#pragma unroll
    for (int o = 16; o; o >>= 1) s += __shfl_xor_sync(0xffffffffu, s, o);
    __shared__ float red[8];
    if ((tid & 31) == 0) red[tid >> 5] = s;
    __syncthreads();
    float tot = 0.0f;
#pragma unroll
    for (int i = 0; i < 8; i++) tot += red[i];
    float inv = 1.0f / (tot + 1e-8f);
#pragma unroll
    for (int i = 0; i < 8; i++) row[tid + 256 * i] = loc[i] * inv;
}

// ---------------- UV[n] = U_n (256x8) @ V_n (8x256) ----------------
__global__ void uv_kernel(const float* __restrict__ pool, float* __restrict__ UV)
{
    int n = blockIdx.x, tid = threadIdx.x;  // 256 threads
    __shared__ float Us[DB * RR];           // 2048 floats
    const float* p = pool + (size_t)n * DP;
    for (int i = tid; i < DB * RR; i += 256) Us[i] = p[i];
    float v[RR];
#pragma unroll
    for (int r = 0; r < RR; r++) v[r] = p[2048 + r * 256 + tid];
    __syncthreads();
    float* out = UV + (size_t)n * 65536 + tid;
#pragma unroll 2
    for (int d = 0; d < DB; d++) {
        float acc = 0.0f;
#pragma unroll
        for (int r = 0; r < RR; r++) acc += Us[d * RR + r] * v[r];
        out[(size_t)d * 256] = acc;
    }
}

// ---------------- BIG GEMM: W_out[256, 65536] = alpha[256,2048] @ UV[2048,65536] + W_base ----------------
// 128x128x8 tiles, 256 threads, 8x8 micro-tile via packed fma.rn.f32x2 (2x fp32 FMA rate)
__global__ void sgemm_big(const float* __restrict__ A, const float* __restrict__ Bm,
                          const float* __restrict__ Wbase, float* __restrict__ C)
{
    __shared__ float As[8][128];
    __shared__ float Bs[8][128];
    int tid = threadIdx.x;
    int n0 = blockIdx.x * 128;
    int m0 = blockIdx.y * 128;
    int arow = tid >> 1, acol = (tid & 1) * 4;
    int brow = tid >> 5, bcol = (tid & 31) * 4;
    int ty8 = (tid >> 4) * 8, tx8 = (tid & 15) * 8;

    unsigned long long acc[8][4];
#pragma unroll
    for (int i = 0; i < 8; i++)
#pragma unroll
        for (int j = 0; j < 4; j++) acc[i][j] = 0ULL;

    const float* Ap = A + (size_t)(m0 + arow) * NP + acol;
    const float* Bp = Bm + (size_t)brow * 65536 + n0 + bcol;
    float4 av = *(const float4*)Ap;
    float4 bv = *(const float4*)Bp;

    for (int k0 = 0; k0 < NP; k0 += 8) {
        As[acol + 0][arow] = av.x; As[acol + 1][arow] = av.y;
        As[acol + 2][arow] = av.z; As[acol + 3][arow] = av.w;
        *(float4*)&Bs[brow][bcol] = bv;
        __syncthreads();
        if (k0 + 8 < NP) {
            av = *(const float4*)(Ap + (k0 + 8));
            bv = *(const float4*)(Bp + (size_t)(k0 + 8) * 65536);
        }
#pragma unroll
        for (int kk = 0; kk < 8; kk++) {
            float ar[8];
            *(float4*)(ar)     = *(const float4*)&As[kk][ty8];
            *(float4*)(ar + 4) = *(const float4*)&As[kk][ty8 + 4];
            unsigned long long bb[4];
            const unsigned long long* bp = (const unsigned long long*)&Bs[kk][tx8];
            bb[0] = bp[0]; bb[1] = bp[1]; bb[2] = bp[2]; bb[3] = bp[3];
#pragma unroll
            for (int i = 0; i < 8; i++) {
                unsigned long long ad = dupf2(ar[i]);
                fma2(acc[i][0], ad, bb[0]);
                fma2(acc[i][1], ad, bb[1]);
                fma2(acc[i][2], ad, bb[2]);
                fma2(acc[i][3], ad, bb[3]);
            }
        }
        __syncthreads();
    }

#pragma unroll
    for (int i = 0; i < 8; i++) {
        size_t rowoff = (size_t)(m0 + ty8 + i) * 65536;
#pragma unroll
        for (int j = 0; j < 4; j++) {
            int col = n0 + tx8 + 2 * j;
            float2 c = unpk(acc[i][j]);
            c.x += Wbase[col];
            c.y += Wbase[col + 1];
            *(float2*)(C + rowoff + col) = c;
        }
    }
}

// ---------------- h_t from W_assembled + b_assembled, residual, LayerNorm ----------------
__global__ void ht_ln_kernel(const float* __restrict__ Wout, const float* __restrict__ hA,
                             const float* __restrict__ bdelta, const float* __restrict__ b_base,
                             const float* __restrict__ gamma_p, const float* __restrict__ ln_s,
                             const float* __restrict__ ln_b, float* __restrict__ hmid)
{
    int b = blockIdx.x, tid = threadIdx.x;     // 256 threads
    int lane = tid & 31, warp = tid >> 5;
    __shared__ float hs[DA];
    __shared__ float ys[DA];
    hs[tid] = hA[(size_t)b * DA + tid];
    __syncthreads();
    float gamma = gamma_p[0];
    const float* Wb = Wout + (size_t)b * 65536;
    for (int c = warp; c < DB; c += 8) {
        const float* row = Wb + (size_t)c * DA;
        float s = 0.0f;
#pragma unroll
        for (int i = 0; i < 8; i++) { int a = lane + 32 * i; s += row[a] * hs[a]; }
#pragma unroll
        for (int o = 16; o; o >>= 1) s += __shfl_xor_sync(0xffffffffu, s, o);
        if (lane == 0) {
            float htv = s + bdelta[(size_t)b * DB + c] + b_base[c];
            ys[c] = hs[c] + gamma * htv;
        }
    }
    __syncthreads();
    float v = ys[tid];
    float s1 = v, s2 = v * v;
#pragma unroll
    for (int o = 16; o; o >>= 1) {
        s1 += __shfl_xor_sync(0xffffffffu, s1, o);
        s2 += __shfl_xor_sync(0xffffffffu, s2, o);
    }
    __shared__ float red[18];
    if (lane == 0) { red[warp] = s1; red[8 + warp] = s2; }
    __syncthreads();
    if (tid == 0) {
        float a = 0.0f, q = 0.0f;
#pragma unroll
        for (int i = 0; i < 8; i++) { a += red[i]; q += red[8 + i]; }
        red[16] = a / (float)DA;
        red[17] = q / (float)DA;
    }
    __syncthreads();
    float mu = red[16];
    float var = fmaxf(red[17] - mu * mu, 0.0f);
    float r = rsqrtf(var + 1e-6f);
    hmid[(size_t)b * DA + tid] = (v - mu) * r * ln_s[tid] + ln_b[tid];
}

// ---------------- launch ----------------
extern "C" void kernel_launch(void* const* d_in, const int* in_sizes, int n_in,
                              void* d_out, int out_size)
{
    const float* x      = (const float*)d_in[0];
    const float* pool   = (const float*)d_in[1];
    const float* A_w0   = (const float*)d_in[2];
    const float* A_b0   = (const float*)d_in[3];
    const float* A_w1   = (const float*)d_in[4];
    const float* A_b1   = (const float*)d_in[5];
    const float* W_Q    = (const float*)d_in[6];
    const float* W_K    = (const float*)d_in[7];
    const float* logits = (const float*)d_in[8];
    const float* tau    = (const float*)d_in[9];
    const float* W_base = (const float*)d_in[10];
    const float* b_base = (const float*)d_in[11];
    const float* gamma  = (const float*)d_in[12];
    const float* ln_s   = (const float*)d_in[13];
    const float* ln_b   = (const float*)d_in[14];
    const float* B_w0   = (const float*)d_in[15];
    const float* B_b0   = (const float*)d_in[16];
    const float* B_w1   = (const float*)d_in[17];
    const float* B_b1   = (const float*)d_in[18];

    float* out       = (float*)d_out;
    float* out_alpha = out + OUT_ALPHA;
    float* out_W     = out + OUT_W;
    float* out_keys  = out + OUT_KEYS;

    float *p_hid, *p_hA, *p_qw, *p_kn, *p_bt, *p_hmid, *p_hid2, *p_UV;
    cudaGetSymbolAddress((void**)&p_hid,  g_hid);
    cudaGetSymbolAddress((void**)&p_hA,   g_hA);
    cudaGetSymbolAddress((void**)&p_qw,   g_qw);
    cudaGetSymbolAddress((void**)&p_kn,   g_kn);
    cudaGetSymbolAddress((void**)&p_bt,   g_bt);
    cudaGetSymbolAddress((void**)&p_hmid, g_hmid);
    cudaGetSymbolAddress((void**)&p_hid2, g_hid2);
    cudaGetSymbolAddress((void**)&p_UV,   g_UV);

    // 1) hid = gelu(x @ A_w0 + A_b0)
    gemm64<1><<<dim3(HIDN / 64, BATCH / 64), 256>>>(x, A_w0, A_b0, p_hid, DMODEL, DMODEL, HIDN, HIDN);
    // 2) h_A = hid @ A_w1 + A_b1
    gemm64<0><<<dim3(DA / 64, BATCH / 64), 256>>>(p_hid, A_w1, A_b1, p_hA, HIDN, HIDN, DA, DA);
    // 3) weighted normalized queries
    q_kernel<<<dim3(BATCH, SA), 64>>>(p_hA, W_Q, logits, p_qw);
    // 4) keys (output) — independent, also feeds k_norm
    keys_gemm_kernel<<<dim3(SA, NP / 64), 256>>>(pool, W_K, out_keys);
    // 5) k_norm
    knorm_kernel<<<dim3(NP, SA), 64>>>(out_keys, p_kn);
    // 6) scores -> alpha_raw (into alpha output region)
    scores_kernel<<<dim3(NP / 64, BATCH / 64), 256>>>(p_qw, p_kn, tau, out_alpha);
    // 7) normalize alpha rows
    alpha_norm_kernel<<<BATCH, 256>>>(out_alpha);
    // 8) UV[n] = U_n @ V_n
    uv_kernel<<<NP, 256>>>(pool, p_UV);
    // 9) W_assembled = W_base + alpha @ UV  (dominant GEMM, f32x2 FMAs)
    sgemm_big<<<dim3(65536 / 128, BATCH / 128), 256>>>(out_alpha, p_UV, W_base, out_W);
    // 10) b_delta = alpha @ bias   (bias = pool[:, 4096:4352], ldb = 4608)
    gemm64<0><<<dim3(DB / 64, BATCH / 64), 256>>>(out_alpha, pool + 4096, nullptr, p_bt, NP, NP, DP, DB);
    // 11) h_t, residual, layernorm
    ht_ln_kernel<<<BATCH, 256>>>(out_W, p_hA, p_bt, b_base, gamma, ln_s, ln_b, p_hmid);
    // 12) hid2 = gelu(h_mid @ B_w0 + B_b0)
    gemm64<1><<<dim3(HIDN / 64, BATCH / 64), 256>>>(p_hmid, B_w0, B_b0, p_hid2, DA, DA, HIDN, HIDN);
    // 13) output = hid2 @ B_w1 + B_b1
    gemm64<0><<<dim3(DMODEL / 64, BATCH / 64), 256>>>(p_hid2, B_w1, B_b1, out, HIDN, HIDN, DMODEL, DMODEL);
}

// round 4
// speedup vs baseline: 1.9953x; 1.9953x over previous
#include <cuda_runtime.h>
#include <cuda_bf16.h>
#include <cstdint>
#include <cstddef>

// ---------------- problem constants ----------------
#define BATCH  256
#define DMODEL 512
#define DA     256
#define DB     256
#define RR     8
#define NP     2048
#define DP     4608
#define SA     4
#define DKK    64
#define HIDN   1024
#define NDE    65536           // DB*DA
#define KSPLIT 4
#define KCHUNK (DP / KSPLIT)   // 1152

// output layout (flattened tuple: output, alpha, W_assembled, keys)
#define OUT_ALPHA  (BATCH*DMODEL)                       // 131072
#define OUT_W      (OUT_ALPHA + BATCH*NP)               // 655360
#define OUT_KEYS   (OUT_W + (size_t)BATCH*DB*DA)        // 17432576

// ---------------- scratch (device globals; no allocation allowed) ----------------
__device__ float g_hid [BATCH*HIDN];
__device__ float g_hA  [BATCH*DA];
__device__ float g_qw  [BATCH*SA*DKK];
__device__ float g_kn  [NP*SA*DKK];
__device__ float g_bt  [BATCH*DB];
__device__ float g_hmid[BATCH*DA];
__device__ float g_hid2[BATCH*HIDN];
__device__ float g_kp  [KSPLIT*NP*SA*DKK];              // keys split-K partials (8MB)
__device__ __nv_bfloat16 g_alphab[BATCH*NP];            // alpha in bf16
__device__ __nv_bfloat16 g_UVb[(size_t)NP*NDE];         // UV in bf16 (268MB)

// ---------------- helpers ----------------
__device__ __forceinline__ float gelu_f(float x) {
    const float c = 0.7978845608028654f;
    return 0.5f * x * (1.0f + tanhf(c * (x + 0.044715f * x * x * x)));
}
__device__ __forceinline__ uint32_t smem_u32(const void* p) {
    uint32_t a;
    asm("{ .reg .u64 t; cvta.to.shared.u64 t, %1; cvt.u32.u64 %0, t; }" : "=r"(a) : "l"(p));
    return a;
}
__device__ __forceinline__ void ldmat_x4(uint32_t& r0, uint32_t& r1, uint32_t& r2, uint32_t& r3,
                                         uint32_t addr) {
    asm volatile("ldmatrix.sync.aligned.m8n8.x4.shared.b16 {%0,%1,%2,%3}, [%4];"
                 : "=r"(r0), "=r"(r1), "=r"(r2), "=r"(r3) : "r"(addr));
}
__device__ __forceinline__ void mma_bf16(float* d, const uint32_t* a, const uint32_t* b) {
    asm volatile("mma.sync.aligned.m16n8k16.row.col.f32.bf16.bf16.f32 "
                 "{%0,%1,%2,%3}, {%4,%5,%6,%7}, {%8,%9}, {%0,%1,%2,%3};"
                 : "+f"(d[0]), "+f"(d[1]), "+f"(d[2]), "+f"(d[3])
                 : "r"(a[0]), "r"(a[1]), "r"(a[2]), "r"(a[3]), "r"(b[0]), "r"(b[1]));
}

// ---------------- generic 64x64x16 SGEMM (small MLPs) ----------------
template <int ACT>
__global__ void gemm64(const float* __restrict__ A, const float* __restrict__ B,
                       const float* __restrict__ bias, float* __restrict__ C,
                       int K, int lda, int ldb, int ldc)
{
    __shared__ float As[16][64];
    __shared__ float Bs[16][64];
    int tid = threadIdx.x;
    int m0 = blockIdx.y * 64, n0 = blockIdx.x * 64;
    int am = tid >> 2, ak = (tid & 3) * 4;
    int bk = tid >> 4, bn = (tid & 15) * 4;
    int ty = tid >> 4, tx = tid & 15;
    float acc[4][4] = {};
    const float* Ap = A + (size_t)(m0 + am) * lda + ak;
    const float* Bp = B + (size_t)bk * ldb + n0 + bn;
    float4 av = *(const float4*)Ap;
    float4 bv = *(const float4*)Bp;
    for (int k0 = 0; k0 < K; k0 += 16) {
        As[ak + 0][am] = av.x; As[ak + 1][am] = av.y; As[ak + 2][am] = av.z; As[ak + 3][am] = av.w;
        *(float4*)&Bs[bk][bn] = bv;
        __syncthreads();
        if (k0 + 16 < K) {
            av = *(const float4*)(Ap + (k0 + 16));
            bv = *(const float4*)(Bp + (size_t)(k0 + 16) * ldb);
        }
#pragma unroll
        for (int kk = 0; kk < 16; kk++) {
            float ar[4], br[4];
            *(float4*)ar = *(const float4*)&As[kk][ty * 4];
            *(float4*)br = *(const float4*)&Bs[kk][tx * 4];
#pragma unroll
            for (int i = 0; i < 4; i++)
#pragma unroll
                for (int j = 0; j < 4; j++) acc[i][j] += ar[i] * br[j];
        }
        __syncthreads();
    }
#pragma unroll
    for (int i = 0; i < 4; i++) {
        int m = m0 + ty * 4 + i;
#pragma unroll
        for (int j = 0; j < 4; j++) {
            int n = n0 + tx * 4 + j;
            float c = acc[i][j];
            if (bias) c += bias[n];
            if (ACT == 1) c = gelu_f(c);
            C[(size_t)m * ldc + n] = c;
        }
    }
}

// ---------------- keys GEMM split-K: partial[ks][n][a*64+q] ----------------
__global__ void keys_gemm_kernel(const float* __restrict__ pool, const float* __restrict__ WK,
                                 float* __restrict__ kp)
{
    int a  = blockIdx.x;
    int m0 = blockIdx.y * 64;
    int ks = blockIdx.z;
    int kbeg = ks * KCHUNK;
    const float* B = WK + (size_t)a * DP * DKK;
    __shared__ float As[16][64];
    __shared__ float Bs[16][64];
    int tid = threadIdx.x;
    int am = tid >> 2, ak = (tid & 3) * 4;
    int bk = tid >> 4, bn = (tid & 15) * 4;
    int ty = tid >> 4, tx = tid & 15;
    float acc[4][4] = {};
    const float* Ap = pool + (size_t)(m0 + am) * DP + kbeg + ak;
    const float* Bp = B + (size_t)(kbeg + bk) * DKK + bn;
    float4 av = *(const float4*)Ap;
    float4 bv = *(const float4*)Bp;
    for (int k0 = 0; k0 < KCHUNK; k0 += 16) {
        As[ak + 0][am] = av.x; As[ak + 1][am] = av.y; As[ak + 2][am] = av.z; As[ak + 3][am] = av.w;
        *(float4*)&Bs[bk][bn] = bv;
        __syncthreads();
        if (k0 + 16 < KCHUNK) {
            av = *(const float4*)(Ap + (k0 + 16));
            bv = *(const float4*)(Bp + (size_t)(k0 + 16) * DKK);
        }
#pragma unroll
        for (int kk = 0; kk < 16; kk++) {
            float ar[4], br[4];
            *(float4*)ar = *(const float4*)&As[kk][ty * 4];
            *(float4*)br = *(const float4*)&Bs[kk][tx * 4];
#pragma unroll
            for (int i = 0; i < 4; i++)
#pragma unroll
                for (int j = 0; j < 4; j++) acc[i][j] += ar[i] * br[j];
        }
        __syncthreads();
    }
    float* outp = kp + (size_t)ks * NP * (SA * DKK);
#pragma unroll
    for (int i = 0; i < 4; i++)
#pragma unroll
        for (int j = 0; j < 4; j++)
            outp[(size_t)(m0 + ty * 4 + i) * (SA * DKK) + a * DKK + tx * 4 + j] = acc[i][j];
}

// ---------------- reduce partials -> keys output + normalized keys ----------------
__global__ void knorm_kernel(const float* __restrict__ kp, float* __restrict__ keys,
                             float* __restrict__ kn)
{
    int n = blockIdx.x, a = blockIdx.y, tid = threadIdx.x;  // 64 threads
    size_t idx = (size_t)n * (SA * DKK) + a * DKK + tid;
    float v = 0.0f;
#pragma unroll
    for (int ks = 0; ks < KSPLIT; ks++) v += kp[(size_t)ks * NP * (SA * DKK) + idx];
    keys[idx] = v;
    float ss = v * v;
#pragma unroll
    for (int o = 16; o; o >>= 1) ss += __shfl_xor_sync(0xffffffffu, ss, o);
    __shared__ float r2[2];
    if ((tid & 31) == 0) r2[tid >> 5] = ss;
    __syncthreads();
    float nrm = sqrtf(r2[0] + r2[1]);
    kn[idx] = v / (nrm + 1e-8f);
}

// ---------------- queries ----------------
__global__ void q_kernel(const float* __restrict__ hA, const float* __restrict__ WQ,
                         const float* __restrict__ logits, float* __restrict__ qw)
{
    int b = blockIdx.x, a = blockIdx.y, tid = threadIdx.x;  // 64 threads
    __shared__ float hs[DA];
    for (int i = tid; i < DA; i += 64) hs[i] = hA[(size_t)b * DA + i];
    __syncthreads();
    float q = 0.0f;
    const float* w = WQ + (size_t)a * DA * DKK + tid;
#pragma unroll 4
    for (int d = 0; d < DA; d++) q += hs[d] * w[(size_t)d * DKK];
    float ss = q * q;
#pragma unroll
    for (int o = 16; o; o >>= 1) ss += __shfl_xor_sync(0xffffffffu, ss, o);
    __shared__ float r2[2];
    if ((tid & 31) == 0) r2[tid >> 5] = ss;
    __syncthreads();
    float nrm = sqrtf(r2[0] + r2[1]);
    float l0 = logits[0], l1 = logits[1], l2 = logits[2], l3 = logits[3];
    float m = fmaxf(fmaxf(l0, l1), fmaxf(l2, l3));
    float e0 = expf(l0 - m), e1 = expf(l1 - m), e2 = expf(l2 - m), e3 = expf(l3 - m);
    float ea = (a == 0) ? e0 : (a == 1) ? e1 : (a == 2) ? e2 : e3;
    float wa = ea / (e0 + e1 + e2 + e3);
    qw[(size_t)b * (SA * DKK) + a * DKK + tid] = wa * q / (nrm + 1e-8f);
}

// ---------------- scores + gate/exp -> alpha_raw ----------------
__global__ void scores_kernel(const float* __restrict__ QW, const float* __restrict__ KN,
                              const float* __restrict__ tau_p, float* __restrict__ alpha)
{
    int n0 = blockIdx.x * 64, m0 = blockIdx.y * 64;
    __shared__ float As[16][64];
    __shared__ float Bs[16][64];
    int tid = threadIdx.x;
    int am = tid >> 2, ak = (tid & 3) * 4;
    int bn = tid >> 2, bk = (tid & 3) * 4;
    int ty = tid >> 4, tx = tid & 15;
    float acc[4][4] = {};
    for (int k0 = 0; k0 < 256; k0 += 16) {
        float4 av = *(const float4*)(QW + (size_t)(m0 + am) * 256 + k0 + ak);
        As[ak + 0][am] = av.x; As[ak + 1][am] = av.y; As[ak + 2][am] = av.z; As[ak + 3][am] = av.w;
        float4 bv = *(const float4*)(KN + (size_t)(n0 + bn) * 256 + k0 + bk);
        Bs[bk + 0][bn] = bv.x; Bs[bk + 1][bn] = bv.y; Bs[bk + 2][bn] = bv.z; Bs[bk + 3][bn] = bv.w;
        __syncthreads();
#pragma unroll
        for (int kk = 0; kk < 16; kk++) {
            float ar[4], br[4];
            *(float4*)ar = *(const float4*)&As[kk][ty * 4];
            *(float4*)br = *(const float4*)&Bs[kk][tx * 4];
#pragma unroll
            for (int i = 0; i < 4; i++)
#pragma unroll
                for (int j = 0; j < 4; j++) acc[i][j] += ar[i] * br[j];
        }
        __syncthreads();
    }
    float tau = tau_p[0];
#pragma unroll
    for (int i = 0; i < 4; i++)
#pragma unroll
        for (int j = 0; j < 4; j++) {
            float s = acc[i][j];
            float g = 1.0f / (1.0f + expf(-(s - tau)));
            alpha[(size_t)(m0 + ty * 4 + i) * NP + n0 + tx * 4 + j] = g * expf(s);
        }
}

// ---------------- alpha row normalization (+ bf16 copy) ----------------
__global__ void alpha_norm_kernel(float* __restrict__ alpha, __nv_bfloat16* __restrict__ ab)
{
    int b = blockIdx.x, tid = threadIdx.x;  // 256 threads
    float* row = alpha + (size_t)b * NP;
    __nv_bfloat16* rowb = ab + (size_t)b * NP;
    float loc[8]; float s = 0.0f;
#pragma unroll
    for (int i = 0; i < 8; i++) { loc[i] = row[tid + 256 * i]; s += loc[i]; }
#pragma unroll
    for (int o = 16; o; o >>= 1) s += __shfl_xor_sync(0xffffffffu, s, o);
    __shared__ float red[8];
    if ((tid & 31) == 0) red[tid >> 5] = s;
    __syncthreads();
    float tot = 0.0f;
#pragma unroll
    for (int i = 0; i < 8; i++) tot += red[i];
    float inv = 1.0f / (tot + 1e-8f);
#pragma unroll
    for (int i = 0; i < 8; i++) {
        float v = loc[i] * inv;
        row[tid + 256 * i] = v;
        rowb[tid + 256 * i] = __float2bfloat16(v);
    }
}

// ---------------- UV[n] = U_n @ V_n -> bf16, natural [k][de] layout ----------------
__global__ void uv_kernel(const float* __restrict__ pool, __nv_bfloat16* __restrict__ UV)
{
    int n = blockIdx.x, tid = threadIdx.x;  // 256 threads
    __shared__ float Us[DB * RR];
    const float* p = pool + (size_t)n * DP;
    for (int i = tid; i < DB * RR; i += 256) Us[i] = p[i];
    float v[RR];
#pragma unroll
    for (int r = 0; r < RR; r++) v[r] = p[2048 + r * 256 + tid];
    __syncthreads();
    __nv_bfloat16* out = UV + (size_t)n * NDE + tid;
#pragma unroll 2
    for (int d = 0; d < DB; d++) {
        float acc = 0.0f;
#pragma unroll
        for (int r = 0; r < RR; r++) acc += Us[d * RR + r] * v[r];
        out[(size_t)d * 256] = __float2bfloat16(acc);
    }
}

// ---------------- BIG GEMM via ldmatrix + mma.sync (bf16 -> fp32) ----------------
// C[256,65536] = W_base + A[256,2048] @ B[2048,65536]
// Tile: BM=128, BN=128, BK=32. 256 threads = 8 warps (4m x 2n), warp tile 32x64.
// Smem rows padded to 80B (stride 40 bf16) => conflict-free ldmatrix.
#define BSTRIDE 40          // bf16 elements per smem row (80 bytes)

__global__ void __launch_bounds__(256, 2) big_mma_kernel(
    const __nv_bfloat16* __restrict__ Ab, const __nv_bfloat16* __restrict__ Bb,
    const float* __restrict__ Wbase, float* __restrict__ C)
{
    __shared__ __align__(16) __nv_bfloat16 sA[2][128 * BSTRIDE];  // 10240 B each
    __shared__ __align__(16) __nv_bfloat16 sB[2][128 * BSTRIDE];  // B^T: [n][k]

    int tid = threadIdx.x;
    int lane = tid & 31, wid = tid >> 5;
    int warp_m = wid & 3;       // 4 m-warps: 32 rows each
    int warp_n = wid >> 2;      // 2 n-warps: 64 cols each
    int m0 = blockIdx.y * 128;
    int n0 = blockIdx.x * 128;

    uint32_t sa_base = smem_u32(&sA[0][0]);
    uint32_t sb_base = smem_u32(&sB[0][0]);
    const uint32_t A_BUF = 128 * BSTRIDE * 2;   // bytes per buffer
    const uint32_t B_BUF = 128 * BSTRIDE * 2;

    // ldmatrix per-lane offsets (bytes)
    uint32_t a_lm = (uint32_t)(warp_m * 32 + (lane & 15)) * (BSTRIDE * 2) + (lane >> 4) * 16;
    uint32_t b_lm = (uint32_t)(warp_n * 64 + (lane & 15)) * (BSTRIDE * 2) + (lane >> 4) * 16;

    // A staging: 2 passes, row = (tid>>2)+p*64, seg = tid&3 (16B)
    int as_row = tid >> 2, as_seg = tid & 3;
    // B staging: kg = tid>>4 (16 pairs of k), ng = tid&15 (16 groups of 8 n)
    int bs_kg = tid >> 4, bs_ng = tid & 15;

    float acc[2][8][4];
#pragma unroll
    for (int i = 0; i < 2; i++)
#pragma unroll
        for (int j = 0; j < 8; j++)
#pragma unroll
            for (int q = 0; q < 4; q++) acc[i][j][q] = 0.0f;

    uint4 areg[2], breg[2];
    const int NC = NP / 32;   // 64 chunks

    // prologue: load chunk 0, store to buf 0
    {
        const __nv_bfloat16* Ag = Ab + (size_t)m0 * NP;
        areg[0] = *(const uint4*)(Ag + (size_t)(as_row) * NP + as_seg * 8);
        areg[1] = *(const uint4*)(Ag + (size_t)(as_row + 64) * NP + as_seg * 8);
        const __nv_bfloat16* Bg = Bb + (size_t)(bs_kg * 2) * NDE + n0 + bs_ng * 8;
        breg[0] = *(const uint4*)(Bg);
        breg[1] = *(const uint4*)(Bg + NDE);
    }
    {
        __nv_bfloat16* dA = &sA[0][0];
        *(uint4*)(dA + (size_t)as_row * BSTRIDE + as_seg * 8) = areg[0];
        *(uint4*)(dA + (size_t)(as_row + 64) * BSTRIDE + as_seg * 8) = areg[1];
        const uint32_t* w0 = (const uint32_t*)&breg[0];
        const uint32_t* w1 = (const uint32_t*)&breg[1];
        __nv_bfloat16* dB = &sB[0][0];
#pragma unroll
        for (int j = 0; j < 8; j++) {
            uint32_t sel = (j & 1) ? 0x7632u : 0x5410u;
            uint32_t pr = __byte_perm(w0[j >> 1], w1[j >> 1], sel);
            *(uint32_t*)((char*)dB + (size_t)(bs_ng * 8 + j) * (BSTRIDE * 2) + bs_kg * 4) = pr;
        }
    }
    __syncthreads();

    for (int c = 0; c < NC; c++) {
        int buf = c & 1;
        // prefetch next chunk
        if (c + 1 < NC) {
            int k0 = (c + 1) * 32;
            const __nv_bfloat16* Ag = Ab + (size_t)m0 * NP + k0;
            areg[0] = *(const uint4*)(Ag + (size_t)(as_row) * NP + as_seg * 8);
            areg[1] = *(const uint4*)(Ag + (size_t)(as_row + 64) * NP + as_seg * 8);
            const __nv_bfloat16* Bg = Bb + (size_t)(k0 + bs_kg * 2) * NDE + n0 + bs_ng * 8;
            breg[0] = *(const uint4*)(Bg);
            breg[1] = *(const uint4*)(Bg + NDE);
        }
        // compute on buf
        uint32_t abase = sa_base + buf * A_BUF + a_lm;
        uint32_t bbase = sb_base + buf * B_BUF + b_lm;
#pragma unroll
        for (int k16 = 0; k16 < 2; k16++) {
            uint32_t af[2][4];
            uint32_t bf[8][2];
#pragma unroll
            for (int mt = 0; mt < 2; mt++)
                ldmat_x4(af[mt][0], af[mt][1], af[mt][2], af[mt][3],
                         abase + mt * 16 * (BSTRIDE * 2) + k16 * 32);
#pragma unroll
            for (int bt = 0; bt < 4; bt++) {
                uint32_t r0, r1, r2, r3;
                ldmat_x4(r0, r1, r2, r3, bbase + bt * 16 * (BSTRIDE * 2) + k16 * 32);
                bf[2 * bt + 0][0] = r0; bf[2 * bt + 0][1] = r2;
                bf[2 * bt + 1][0] = r1; bf[2 * bt + 1][1] = r3;
            }
#pragma unroll
            for (int mt = 0; mt < 2; mt++)
#pragma unroll
                for (int nt = 0; nt < 8; nt++)
                    mma_bf16(acc[mt][nt], af[mt], bf[nt]);
        }
        // store next chunk
        if (c + 1 < NC) {
            int nb = (c + 1) & 1;
            __nv_bfloat16* dA = &sA[nb][0];
            *(uint4*)(dA + (size_t)as_row * BSTRIDE + as_seg * 8) = areg[0];
            *(uint4*)(dA + (size_t)(as_row + 64) * BSTRIDE + as_seg * 8) = areg[1];
            const uint32_t* w0 = (const uint32_t*)&breg[0];
            const uint32_t* w1 = (const uint32_t*)&breg[1];
            __nv_bfloat16* dB = &sB[nb][0];
#pragma unroll
            for (int j = 0; j < 8; j++) {
                uint32_t sel = (j & 1) ? 0x7632u : 0x5410u;
                uint32_t pr = __byte_perm(w0[j >> 1], w1[j >> 1], sel);
                *(uint32_t*)((char*)dB + (size_t)(bs_ng * 8 + j) * (BSTRIDE * 2) + bs_kg * 4) = pr;
            }
        }
        __syncthreads();
    }

    // epilogue: acc + W_base -> C
#pragma unroll
    for (int mt = 0; mt < 2; mt++) {
        int row = m0 + warp_m * 32 + mt * 16 + (lane >> 2);
        float* c0 = C + (size_t)row * NDE;
        float* c1 = C + (size_t)(row + 8) * NDE;
#pragma unroll
        for (int nt = 0; nt < 8; nt++) {
            int col = n0 + warp_n * 64 + nt * 8 + (lane & 3) * 2;
            float2 wb = *(const float2*)(Wbase + col);
            float2 o0, o1;
            o0.x = acc[mt][nt][0] + wb.x; o0.y = acc[mt][nt][1] + wb.y;
            o1.x = acc[mt][nt][2] + wb.x; o1.y = acc[mt][nt][3] + wb.y;
            *(float2*)(c0 + col) = o0;
            *(float2*)(c1 + col) = o1;
        }
    }
}

// ---------------- h_t + residual + LayerNorm ----------------
__global__ void ht_ln_kernel(const float* __restrict__ Wout, const float* __restrict__ hA,
                             const float* __restrict__ bdelta, const float* __restrict__ b_base,
                             const float* __restrict__ gamma_p, const float* __restrict__ ln_s,
                             const float* __restrict__ ln_b, float* __restrict__ hmid)
{
    int b = blockIdx.x, tid = threadIdx.x;     // 256 threads
    int lane = tid & 31, warp = tid >> 5;
    __shared__ float hs[DA];
    __shared__ float ys[DA];
    hs[tid] = hA[(size_t)b * DA + tid];
    __syncthreads();
    float gamma = gamma_p[0];
    const float* Wb = Wout + (size_t)b * NDE;
    for (int c = warp; c < DB; c += 8) {
        const float* row = Wb + (size_t)c * DA;
        float s = 0.0f;
#pragma unroll
        for (int i = 0; i < 8; i++) { int a = lane + 32 * i; s += row[a] * hs[a]; }
#pragma unroll
        for (int o = 16; o; o >>= 1) s += __shfl_xor_sync(0xffffffffu, s, o);
        if (lane == 0) {
            float htv = s + bdelta[(size_t)b * DB + c] + b_base[c];
            ys[c] = hs[c] + gamma * htv;
        }
    }
    __syncthreads();
    float v = ys[tid];
    float s1 = v, s2 = v * v;
#pragma unroll
    for (int o = 16; o; o >>= 1) {
        s1 += __shfl_xor_sync(0xffffffffu, s1, o);
        s2 += __shfl_xor_sync(0xffffffffu, s2, o);
    }
    __shared__ float red[18];
    if (lane == 0) { red[warp] = s1; red[8 + warp] = s2; }
    __syncthreads();
    if (tid == 0) {
        float a = 0.0f, q = 0.0f;
#pragma unroll
        for (int i = 0; i < 8; i++) { a += red[i]; q += red[8 + i]; }
        red[16] = a / (float)DA;
        red[17] = q / (float)DA;
    }
    __syncthreads();
    float mu = red[16];
    float var = fmaxf(red[17] - mu * mu, 0.0f);
    float r = rsqrtf(var + 1e-6f);
    hmid[(size_t)b * DA + tid] = (v - mu) * r * ln_s[tid] + ln_b[tid];
}

// ---------------- launch ----------------
extern "C" void kernel_launch(void* const* d_in, const int* in_sizes, int n_in,
                              void* d_out, int out_size)
{
    const float* x      = (const float*)d_in[0];
    const float* pool   = (const float*)d_in[1];
    const float* A_w0   = (const float*)d_in[2];
    const float* A_b0   = (const float*)d_in[3];
    const float* A_w1   = (const float*)d_in[4];
    const float* A_b1   = (const float*)d_in[5];
    const float* W_Q    = (const float*)d_in[6];
    const float* W_K    = (const float*)d_in[7];
    const float* logits = (const float*)d_in[8];
    const float* tau    = (const float*)d_in[9];
    const float* W_base = (const float*)d_in[10];
    const float* b_base = (const float*)d_in[11];
    const float* gamma  = (const float*)d_in[12];
    const float* ln_s   = (const float*)d_in[13];
    const float* ln_b   = (const float*)d_in[14];
    const float* B_w0   = (const float*)d_in[15];
    const float* B_b0   = (const float*)d_in[16];
    const float* B_w1   = (const float*)d_in[17];
    const float* B_b1   = (const float*)d_in[18];

    float* out       = (float*)d_out;
    float* out_alpha = out + OUT_ALPHA;
    float* out_W     = out + OUT_W;
    float* out_keys  = out + OUT_KEYS;

    float *p_hid, *p_hA, *p_qw, *p_kn, *p_bt, *p_hmid, *p_hid2, *p_kp;
    __nv_bfloat16 *p_ab, *p_UVb;
    cudaGetSymbolAddress((void**)&p_hid,  g_hid);
    cudaGetSymbolAddress((void**)&p_hA,   g_hA);
    cudaGetSymbolAddress((void**)&p_qw,   g_qw);
    cudaGetSymbolAddress((void**)&p_kn,   g_kn);
    cudaGetSymbolAddress((void**)&p_bt,   g_bt);
    cudaGetSymbolAddress((void**)&p_hmid, g_hmid);
    cudaGetSymbolAddress((void**)&p_hid2, g_hid2);
    cudaGetSymbolAddress((void**)&p_kp,   g_kp);
    cudaGetSymbolAddress((void**)&p_ab,   g_alphab);
    cudaGetSymbolAddress((void**)&p_UVb,  g_UVb);

    // 1) hid = gelu(x @ A_w0 + A_b0)
    gemm64<1><<<dim3(HIDN / 64, BATCH / 64), 256>>>(x, A_w0, A_b0, p_hid, DMODEL, DMODEL, HIDN, HIDN);
    // 2) h_A = hid @ A_w1 + A_b1
    gemm64<0><<<dim3(DA / 64, BATCH / 64), 256>>>(p_hid, A_w1, A_b1, p_hA, HIDN, HIDN, DA, DA);
    // 3) weighted normalized queries
    q_kernel<<<dim3(BATCH, SA), 64>>>(p_hA, W_Q, logits, p_qw);
    // 4) keys split-K partials
    keys_gemm_kernel<<<dim3(SA, NP / 64, KSPLIT), 256>>>(pool, W_K, p_kp);
    // 5) reduce + keys output + k_norm
    knorm_kernel<<<dim3(NP, SA), 64>>>(p_kp, out_keys, p_kn);
    // 6) scores -> alpha_raw
    scores_kernel<<<dim3(NP / 64, BATCH / 64), 256>>>(p_qw, p_kn, tau, out_alpha);
    // 7) normalize alpha + bf16 copy
    alpha_norm_kernel<<<BATCH, 256>>>(out_alpha, p_ab);
    // 8) UV[n] = U_n @ V_n  (bf16)
    uv_kernel<<<NP, 256>>>(pool, p_UVb);
    // 9) W_assembled = W_base + alpha @ UV  (mma.sync bf16)
    big_mma_kernel<<<dim3(NDE / 128, BATCH / 128), 256>>>(p_ab, p_UVb, W_base, out_W);
    // 10) b_delta = alpha @ bias (pool cols 4096:4352, ldb=4608)
    gemm64<0><<<dim3(DB / 64, BATCH / 64), 256>>>(out_alpha, pool + 4096, nullptr, p_bt, NP, NP, DP, DB);
    // 11) h_t, residual, layernorm
    ht_ln_kernel<<<BATCH, 256>>>(out_W, p_hA, p_bt, b_base, gamma, ln_s, ln_b, p_hmid);
    // 12) hid2 = gelu(h_mid @ B_w0 + B_b0)
    gemm64<1><<<dim3(HIDN / 64, BATCH / 64), 256>>>(p_hmid, B_w0, B_b0, p_hid2, DA, DA, HIDN, HIDN);
    // 13) output = hid2 @ B_w1 + B_b1
    gemm64<0><<<dim3(DMODEL / 64, BATCH / 64), 256>>>(p_hid2, B_w1, B_b1, out, HIDN, HIDN, DMODEL, DMODEL);
}